// round 1
// baseline (speedup 1.0000x reference)
#include <cuda_runtime.h>
#include <math.h>

#define T_LEN 1440
#define B_LEN 2048
#define N_RC  5

// Scratch planes, transposed [t][b] for coalesced access in the recurrence.
__device__ float g_ta[T_LEN * B_LEN];
__device__ float g_so[T_LEN * B_LEN];
__device__ float g_qs[T_LEN * B_LEN];

__device__ __forceinline__ float sp(float x) {
    // softplus, stable
    if (x > 20.f)  return x;
    if (x < -20.f) return expf(x);
    return log1pf(expf(x));
}

// ---------------------------------------------------------------------------
// Pass 1: per-(b,t) drive terms. Tiled 32b x 32t, transpose via smem.
//   reads input_X [B,T,7] coalesced, writes g_ta/g_so/g_qs [T,B] coalesced.
// ---------------------------------------------------------------------------
__global__ __launch_bounds__(256) void k1_drive(
    const float* __restrict__ X,
    const float* __restrict__ W1, const float* __restrict__ B1,
    const float* __restrict__ W2, const float* __restrict__ B2,
    const float* __restrict__ p_int_gain,
    const float* __restrict__ p_hvac_gain,
    const float* __restrict__ p_direct_gain)
{
    __shared__ float in_s[32 * 224];        // [bb][tt*7 + c]
    __shared__ float w1s[64], b1s[32], w2s[32];
    __shared__ float out_s[3][32][33];      // [c][tt][bb], padded rows

    const int tid = threadIdx.x;
    const int b0  = blockIdx.x * 32;
    const int t0  = blockIdx.y * 32;

    if (tid < 64) w1s[tid] = W1[tid];
    if (tid < 32) { b1s[tid] = B1[tid]; w2s[tid] = W2[tid]; }

    // stage input tile: each batch row is 224 contiguous floats
    const float* src = X + ((long)b0 * T_LEN + t0) * 7;
    #pragma unroll
    for (int e = tid; e < 32 * 224; e += 256) {
        int bb = e / 224, r = e - bb * 224;
        in_s[bb * 224 + r] = src[(long)bb * (T_LEN * 7) + r];
    }
    __syncthreads();

    const float b2v = B2[0];
    const float gi  = 0.1f * sp(p_int_gain[0]);
    const float gh  = 0.1f * sp(p_hvac_gain[0]);
    const float gd  = 0.5f * sp(p_direct_gain[0]);

    const int tt    = tid & 31;
    const int bbase = tid >> 5;

    #pragma unroll
    for (int p = 0; p < 4; p++) {
        const int bb = bbase + p * 8;
        const float* e = &in_s[bb * 224 + tt * 7];
        const float ta = e[1], so = e[2];
        const float x0 = e[3], x1 = e[4], x2 = e[5], hv = e[6];

        float acc = b2v;
        #pragma unroll
        for (int h = 0; h < 32; h++) {
            float z = fmaf(w1s[2 * h], x0, fmaf(w1s[2 * h + 1], x1, b1s[h]));
            acc = fmaf(w2s[h], fmaxf(z, 0.f), acc);
        }
        const float sch = 1.f / (1.f + expf(-acc)) + x2;
        const float q = fmaf(gi, sch, fmaf(gh, hv, gd * so));

        out_s[0][tt][bb] = ta;
        out_s[1][tt][bb] = so;
        out_s[2][tt][bb] = q;
    }
    __syncthreads();

    // transposed, coalesced writes: lanes sweep bb
    #pragma unroll
    for (int e = tid; e < 3 * 32 * 32; e += 256) {
        const int c = e >> 10;
        const int rest = e & 1023;
        const int ttt = rest >> 5;
        const int bb  = rest & 31;
        const float v = out_s[c][ttt][bb];
        float* dst = (c == 0) ? g_ta : (c == 1) ? g_so : g_qs;
        dst[(long)(t0 + ttt) * B_LEN + b0 + bb] = v;
    }
}

// ---------------------------------------------------------------------------
// Pass 2: sequential RC recurrence. One thread per batch row, one warp/block.
// ---------------------------------------------------------------------------
__global__ __launch_bounds__(32) void k2_recur(
    const float* __restrict__ X,
    const float* __restrict__ rcR, const float* __restrict__ rcC,
    const float* __restrict__ winR,
    const float* __restrict__ p_abs_wall, const float* __restrict__ p_abs_roof,
    const float* __restrict__ p_zone_C_inv,
    float* __restrict__ out)
{
    const int lane = threadIdx.x;
    const int b0   = blockIdx.x * 32;
    const int b    = b0 + lane;

    // precompute per-step constants
    const float aw = 0.5f * sp(p_abs_wall[0]);
    const float ar = 0.5f * sp(p_abs_roof[0]);
    float ri[N_RC], m[N_RC], kta[N_RC], ks[N_RC];
    float Rsum = 0.f;
    #pragma unroll
    for (int i = 0; i < N_RC; i++) {
        const float r = sp(rcR[i]) * 0.1f;          // 1/R_OPAQUE
        const float c = sp(rcC[i]) * 1e-5f;         // 1/C_OPAQUE
        const float a = (i < 4) ? aw : ar;
        ri[i] = r; Rsum += r;
        const float cd = c * 900.f;                 // c_inv * DT
        kta[i] = cd * r;
        m[i]   = 1.f - 2.f * cd * r;
        ks[i]  = cd * a;
    }
    const float win   = (sp(winR[0]) + sp(winR[1])) * 0.5f;   // 1/R_TRANS
    const float cz    = sp(p_zone_C_inv[0]) * 1e-5f;          // 1/C_ZONE
    const float g     = cz * 900.f;
    const float alpha = 1.f - g * (Rsum + win);
    const float gw    = g * win;

    // initial state
    const float* xb = X + (long)b * (T_LEN * 7);
    float tz  = xb[0];
    const float ta0 = xb[1];
    float Tm[N_RC];
    #pragma unroll
    for (int i = 0; i < N_RC; i++) Tm[i] = fmaf(0.7f, tz, 0.3f * ta0);

    __shared__ float outs[32][33];

    for (int tc = 0; tc < T_LEN / 32; tc++) {
        const bool gt_chunk = (tc < 2);   // gt substitution only for t <= 46
        #pragma unroll 4
        for (int k = 0; k < 32; k++) {
            const int t = tc * 32 + k;
            const long idx = (long)t * B_LEN + b;
            const float ta = g_ta[idx];
            const float so = g_so[idx];
            const float q  = g_qs[idx];

            // Tz update from OLD Tmid and OLD (carried) Tz
            float S = Tm[0] * ri[0];
            S = fmaf(Tm[1], ri[1], S);
            S = fmaf(Tm[2], ri[2], S);
            S = fmaf(Tm[3], ri[3], S);
            S = fmaf(Tm[4], ri[4], S);
            const float tznew = fmaf(alpha, tz, fmaf(g, S, fmaf(gw, ta, g * q)));

            // Tmid update uses OLD carried Tz
            const float tpz = ta + tz;
            #pragma unroll
            for (int i = 0; i < N_RC; i++)
                Tm[i] = fmaf(m[i], Tm[i], fmaf(kta[i], tpz, ks[i] * so));

            outs[lane][k] = tznew;

            // carry: ground truth for t+1 < ENC_LEN(48), i.e. t <= 46
            if (gt_chunk && t <= 46) tz = xb[(t + 1) * 7];
            else                     tz = tznew;
        }
        __syncwarp();
        const int tbase = tc * 32;
        #pragma unroll 4
        for (int bb = 0; bb < 32; bb++)
            out[(long)(b0 + bb) * T_LEN + tbase + lane] = outs[bb][lane];
        __syncwarp();
    }
}

extern "C" void kernel_launch(void* const* d_in, const int* in_sizes, int n_in,
                              void* d_out, int out_size) {
    const float* X          = (const float*)d_in[0];
    const float* rcR        = (const float*)d_in[1];
    const float* rcC        = (const float*)d_in[2];
    const float* winR       = (const float*)d_in[3];
    const float* hvac_gain  = (const float*)d_in[4];
    const float* W1         = (const float*)d_in[5];
    const float* B1         = (const float*)d_in[6];
    const float* W2         = (const float*)d_in[7];
    const float* B2         = (const float*)d_in[8];
    const float* int_gain   = (const float*)d_in[9];
    const float* direct_gain= (const float*)d_in[10];
    const float* abs_wall   = (const float*)d_in[11];
    const float* abs_roof   = (const float*)d_in[12];
    const float* zone_C_inv = (const float*)d_in[13];
    float* out = (float*)d_out;

    dim3 g1(B_LEN / 32, T_LEN / 32);
    k1_drive<<<g1, 256>>>(X, W1, B1, W2, B2, int_gain, hvac_gain, direct_gain);
    k2_recur<<<B_LEN / 32, 32>>>(X, rcR, rcC, winR, abs_wall, abs_roof,
                                 zone_C_inv, out);
}

// round 2
// speedup vs baseline: 2.4230x; 2.4230x over previous
#include <cuda_runtime.h>
#include <math.h>

#define T_LEN 1440
#define B_LEN 2048
#define N_RC  5
#define WARM  48
#define L_CH  48
#define C_CH  29          // (T_LEN - WARM) / L_CH

// Scratch planes, transposed [t][b] for coalesced access in the recurrence.
__device__ float g_ta[T_LEN * B_LEN];
__device__ float g_so[T_LEN * B_LEN];
__device__ float g_qs[T_LEN * B_LEN];
__device__ float g_AL[36];                 // A^L, row-major
__device__ float g_d [C_CH * 6 * B_LEN];   // per-chunk affine offsets
__device__ float g_cs[C_CH * 6 * B_LEN];   // chunk-start states
__device__ float g_x48[6 * B_LEN];         // state entering LTI region

__device__ __forceinline__ float sp(float x) {
    if (x > 20.f)  return x;
    if (x < -20.f) return expf(x);
    return log1pf(expf(x));
}

struct P { float ri[N_RC], m[N_RC], kta[N_RC], ks[N_RC], alpha, g, gw; };

__device__ __forceinline__ void loadP(P& p,
    const float* rcR, const float* rcC, const float* winR,
    const float* paw, const float* par, const float* pcz)
{
    const float aw = 0.5f * sp(paw[0]);
    const float ar = 0.5f * sp(par[0]);
    float Rsum = 0.f;
    #pragma unroll
    for (int i = 0; i < N_RC; i++) {
        const float r = sp(rcR[i]) * 0.1f;
        const float c = sp(rcC[i]) * 1e-5f;
        const float a = (i < 4) ? aw : ar;
        p.ri[i] = r; Rsum += r;
        const float cd = c * 900.f;
        p.kta[i] = cd * r;
        p.m[i]   = 1.f - 2.f * cd * r;
        p.ks[i]  = cd * a;
    }
    const float win = (sp(winR[0]) + sp(winR[1])) * 0.5f;
    const float cz  = sp(pcz[0]) * 1e-5f;
    p.g     = cz * 900.f;
    p.alpha = 1.f - p.g * (Rsum + win);
    p.gw    = p.g * win;
}

// one LTI step: state (tz, tm[5]) <- A*state + c(ta,so,q); returns new tz
__device__ __forceinline__ float stepf(const P& p, float& tz, float tm[N_RC],
                                       float ta, float so, float q)
{
    float S = tm[0] * p.ri[0];
    S = fmaf(tm[1], p.ri[1], S);
    S = fmaf(tm[2], p.ri[2], S);
    S = fmaf(tm[3], p.ri[3], S);
    S = fmaf(tm[4], p.ri[4], S);
    const float tznew = fmaf(p.alpha, tz, fmaf(p.g, S, fmaf(p.gw, ta, p.g * q)));
    const float tpz = ta + tz;
    #pragma unroll
    for (int i = 0; i < N_RC; i++)
        tm[i] = fmaf(p.m[i], tm[i], fmaf(p.kta[i], tpz, p.ks[i] * so));
    tz = tznew;
    return tznew;
}

// ---------------------------------------------------------------------------
// Pass 1: per-(b,t) drive terms. Tiled 32b x 32t, transpose via smem.
// ---------------------------------------------------------------------------
__global__ __launch_bounds__(256) void k1_drive(
    const float* __restrict__ X,
    const float* __restrict__ W1, const float* __restrict__ B1,
    const float* __restrict__ W2, const float* __restrict__ B2,
    const float* __restrict__ p_int_gain,
    const float* __restrict__ p_hvac_gain,
    const float* __restrict__ p_direct_gain)
{
    __shared__ float in_s[32 * 224];
    __shared__ float w1s[64], b1s[32], w2s[32];
    __shared__ float out_s[3][32][33];

    const int tid = threadIdx.x;
    const int b0  = blockIdx.x * 32;
    const int t0  = blockIdx.y * 32;

    if (tid < 64) w1s[tid] = W1[tid];
    if (tid < 32) { b1s[tid] = B1[tid]; w2s[tid] = W2[tid]; }

    const float* src = X + ((long)b0 * T_LEN + t0) * 7;
    #pragma unroll
    for (int e = tid; e < 32 * 224; e += 256) {
        int bb = e / 224, r = e - bb * 224;
        in_s[bb * 224 + r] = src[(long)bb * (T_LEN * 7) + r];
    }
    __syncthreads();

    const float b2v = B2[0];
    const float gi  = 0.1f * sp(p_int_gain[0]);
    const float gh  = 0.1f * sp(p_hvac_gain[0]);
    const float gd  = 0.5f * sp(p_direct_gain[0]);

    const int tt    = tid & 31;
    const int bbase = tid >> 5;

    #pragma unroll
    for (int pi = 0; pi < 4; pi++) {
        const int bb = bbase + pi * 8;
        const float* e = &in_s[bb * 224 + tt * 7];
        const float ta = e[1], so = e[2];
        const float x0 = e[3], x1 = e[4], x2 = e[5], hv = e[6];

        float acc = b2v;
        #pragma unroll
        for (int h = 0; h < 32; h++) {
            float z = fmaf(w1s[2 * h], x0, fmaf(w1s[2 * h + 1], x1, b1s[h]));
            acc = fmaf(w2s[h], fmaxf(z, 0.f), acc);
        }
        const float sch = 1.f / (1.f + expf(-acc)) + x2;
        const float q = fmaf(gi, sch, fmaf(gh, hv, gd * so));

        out_s[0][tt][bb] = ta;
        out_s[1][tt][bb] = so;
        out_s[2][tt][bb] = q;
    }
    __syncthreads();

    #pragma unroll
    for (int e = tid; e < 3 * 32 * 32; e += 256) {
        const int c = e >> 10;
        const int rest = e & 1023;
        const int ttt = rest >> 5;
        const int bb  = rest & 31;
        const float v = out_s[c][ttt][bb];
        float* dst = (c == 0) ? g_ta : (c == 1) ? g_so : g_qs;
        dst[(long)(t0 + ttt) * B_LEN + b0 + bb] = v;
    }
}

// ---------------------------------------------------------------------------
// Setup: A^L via basis-column evolution (homogeneous steps). 1 block.
// ---------------------------------------------------------------------------
__global__ void k_setup(
    const float* __restrict__ rcR, const float* __restrict__ rcC,
    const float* __restrict__ winR,
    const float* __restrict__ paw, const float* __restrict__ par,
    const float* __restrict__ pcz)
{
    const int j = threadIdx.x;
    if (j >= 6) return;
    P p; loadP(p, rcR, rcC, winR, paw, par, pcz);
    float x[6] = {0.f, 0.f, 0.f, 0.f, 0.f, 0.f};
    x[j] = 1.f;
    for (int s = 0; s < L_CH; s++) {
        float tz = x[0];
        float tm[N_RC] = {x[1], x[2], x[3], x[4], x[5]};
        (void)stepf(p, tz, tm, 0.f, 0.f, 0.f);
        x[0] = tz;
        #pragma unroll
        for (int i = 0; i < N_RC; i++) x[1 + i] = tm[i];
    }
    #pragma unroll
    for (int i = 0; i < 6; i++) g_AL[i * 6 + j] = x[i];
}

// ---------------------------------------------------------------------------
// Warm-up: t = 0..47 with exogenous tz (teacher forcing). Emits outputs and
// the state entering the LTI region.
// ---------------------------------------------------------------------------
__global__ __launch_bounds__(256) void k_warm(
    const float* __restrict__ X,
    const float* __restrict__ rcR, const float* __restrict__ rcC,
    const float* __restrict__ winR,
    const float* __restrict__ paw, const float* __restrict__ par,
    const float* __restrict__ pcz,
    float* __restrict__ out)
{
    P p; loadP(p, rcR, rcC, winR, paw, par, pcz);
    const int b = blockIdx.x * 256 + threadIdx.x;
    const float* xb = X + (long)b * (T_LEN * 7);

    const float tz0 = xb[0], ta0 = xb[1];
    float tm[N_RC];
    #pragma unroll
    for (int i = 0; i < N_RC; i++) tm[i] = fmaf(0.7f, tz0, 0.3f * ta0);

    float tzlast = tz0;
    float* ob = out + (long)b * T_LEN;
    for (int t = 0; t < WARM; t++) {
        float tz = xb[t * 7];            // exogenous carry
        const long idx = (long)t * B_LEN + b;
        tzlast = stepf(p, tz, tm, g_ta[idx], g_so[idx], g_qs[idx]);
        ob[t] = tzlast;
    }
    g_x48[b] = tzlast;
    #pragma unroll
    for (int i = 0; i < N_RC; i++) g_x48[(1 + i) * B_LEN + b] = tm[i];
}

// ---------------------------------------------------------------------------
// Phase A: per-chunk affine offset d_j (run L steps from zero state).
// ---------------------------------------------------------------------------
__global__ __launch_bounds__(256) void k_chunkd(
    const float* __restrict__ rcR, const float* __restrict__ rcC,
    const float* __restrict__ winR,
    const float* __restrict__ paw, const float* __restrict__ par,
    const float* __restrict__ pcz)
{
    P p; loadP(p, rcR, rcC, winR, paw, par, pcz);
    const int b = blockIdx.x * 256 + threadIdx.x;
    const int j = blockIdx.y;
    const int t0 = WARM + j * L_CH;

    float tz = 0.f;
    float tm[N_RC] = {0.f, 0.f, 0.f, 0.f, 0.f};
    for (int s = 0; s < L_CH; s++) {
        const long idx = (long)(t0 + s) * B_LEN + b;
        (void)stepf(p, tz, tm, g_ta[idx], g_so[idx], g_qs[idx]);
    }
    g_d[(j * 6 + 0) * B_LEN + b] = tz;
    #pragma unroll
    for (int i = 0; i < N_RC; i++) g_d[(j * 6 + 1 + i) * B_LEN + b] = tm[i];
}

// ---------------------------------------------------------------------------
// Phase B: sequential scan over chunks: x <- A^L x + d_j  (29 iterations).
// ---------------------------------------------------------------------------
__global__ __launch_bounds__(256) void k_scan()
{
    const int b = blockIdx.x * 256 + threadIdx.x;
    float AL[36];
    #pragma unroll
    for (int i = 0; i < 36; i++) AL[i] = g_AL[i];

    float x[6];
    #pragma unroll
    for (int i = 0; i < 6; i++) x[i] = g_x48[i * B_LEN + b];

    for (int j = 0; j < C_CH; j++) {
        float y[6];
        #pragma unroll
        for (int i = 0; i < 6; i++) {
            g_cs[(j * 6 + i) * B_LEN + b] = x[i];
            float a = g_d[(j * 6 + i) * B_LEN + b];
            #pragma unroll
            for (int k = 0; k < 6; k++) a = fmaf(AL[i * 6 + k], x[k], a);
            y[i] = a;
        }
        #pragma unroll
        for (int i = 0; i < 6; i++) x[i] = y[i];
    }
}

// ---------------------------------------------------------------------------
// Phase C: replay each chunk from its true start state, emit Tz outputs.
// ---------------------------------------------------------------------------
__global__ __launch_bounds__(128) void k_emit(
    const float* __restrict__ rcR, const float* __restrict__ rcC,
    const float* __restrict__ winR,
    const float* __restrict__ paw, const float* __restrict__ par,
    const float* __restrict__ pcz,
    float* __restrict__ out)
{
    P p; loadP(p, rcR, rcC, winR, paw, par, pcz);
    const int b0 = blockIdx.x * 128;
    const int b  = b0 + threadIdx.x;
    const int j  = blockIdx.y;
    const int t0 = WARM + j * L_CH;

    float tz = g_cs[(j * 6 + 0) * B_LEN + b];
    float tm[N_RC];
    #pragma unroll
    for (int i = 0; i < N_RC; i++) tm[i] = g_cs[(j * 6 + 1 + i) * B_LEN + b];

    __shared__ float outs[128][L_CH + 1];
    for (int s = 0; s < L_CH; s++) {
        const long idx = (long)(t0 + s) * B_LEN + b;
        outs[threadIdx.x][s] = stepf(p, tz, tm, g_ta[idx], g_so[idx], g_qs[idx]);
    }
    __syncthreads();

    const int warp = threadIdx.x >> 5, lane = threadIdx.x & 31;
    #pragma unroll 4
    for (int r = 0; r < 32; r++) {
        float* o = out + (long)(b0 + warp * 32 + r) * T_LEN + t0;
        #pragma unroll
        for (int k = lane; k < L_CH; k += 32) o[k] = outs[warp * 32 + r][k];
    }
}

extern "C" void kernel_launch(void* const* d_in, const int* in_sizes, int n_in,
                              void* d_out, int out_size) {
    const float* X          = (const float*)d_in[0];
    const float* rcR        = (const float*)d_in[1];
    const float* rcC        = (const float*)d_in[2];
    const float* winR       = (const float*)d_in[3];
    const float* hvac_gain  = (const float*)d_in[4];
    const float* W1         = (const float*)d_in[5];
    const float* B1         = (const float*)d_in[6];
    const float* W2         = (const float*)d_in[7];
    const float* B2         = (const float*)d_in[8];
    const float* int_gain   = (const float*)d_in[9];
    const float* direct_gain= (const float*)d_in[10];
    const float* abs_wall   = (const float*)d_in[11];
    const float* abs_roof   = (const float*)d_in[12];
    const float* zone_C_inv = (const float*)d_in[13];
    float* out = (float*)d_out;

    dim3 g1(B_LEN / 32, T_LEN / 32);
    k1_drive<<<g1, 256>>>(X, W1, B1, W2, B2, int_gain, hvac_gain, direct_gain);
    k_setup<<<1, 32>>>(rcR, rcC, winR, abs_wall, abs_roof, zone_C_inv);
    k_warm<<<B_LEN / 256, 256>>>(X, rcR, rcC, winR, abs_wall, abs_roof,
                                 zone_C_inv, out);
    dim3 gA(B_LEN / 256, C_CH);
    k_chunkd<<<gA, 256>>>(rcR, rcC, winR, abs_wall, abs_roof, zone_C_inv);
    k_scan<<<B_LEN / 256, 256>>>();
    dim3 gC(B_LEN / 128, C_CH);
    k_emit<<<gC, 128>>>(rcR, rcC, winR, abs_wall, abs_roof, zone_C_inv, out);
}